// round 15
// baseline (speedup 1.0000x reference)
#include <cuda_runtime.h>
#include <cuda_fp16.h>
#include <stdint.h>

// ============================================================================
// Additive flow: 65 sequential steps of a 63->256->256->1 MLP per batch row.
// Warp-level mma.sync.m16n8k16 fp16 (HMMA), single product (A and W rounded
// once to fp16, fp32 accumulate; measured rel_err ~1.9e-4, 5x under gate).
// Weights pre-packed into per-lane MMA fragment order by prologue kernels so
// B operands are coalesced LDG.64s shared across CTAs (L1/L2 broadcast).
//
// This round: ONE 512-thread CTA per SM containing FOUR independent 4-warp
// streams, each owning 32 batch rows. Streams synchronize only via their own
// named barrier (bar.sync id,128) -- no CTA-wide __syncthreads in the step
// loop -- so one stream's MMA phase overlaps another's epilogue phase and the
// tensor pipe (previously idle 43% of the time) stays fed.
// ============================================================================

#define NSTEPS_MAX 65

// W1 fragments: [step][kt(4)][ntile(32)][lane(32)] x 8B   (fp16)
__device__ __align__(16) unsigned char g_w1f[NSTEPS_MAX * 4 * 32 * 32 * 8];
// W2 fragments: [step][kt(16)][ntile(32)][lane(32)] x 8B
__device__ __align__(16) unsigned char g_w2f[(size_t)NSTEPS_MAX * 16 * 32 * 32 * 8];
// [step][ntile(32)][lane(32)] x float4 {b2[n0], b2[n0+1], w3[n0], w3[n0+1]}
__device__ __align__(16) unsigned char g_bw3[NSTEPS_MAX * 32 * 32 * 16];

#define W1_STEP_BYTES  (4 * 32 * 32 * 8)     // 32768
#define W2_STEP_BYTES  (16 * 32 * 32 * 8)    // 131072

// ---- SMEM layout (bytes), 128-row CTA tile = 4 streams x 32 rows ----
#define ZS_OFF    0        // z: [64 cols][128 rows] fp32 = 32768
#define VH_OFF    32768    // v per stream: [32 rows][64 k] fp16 = 4096 x4
#define H1_OFF    49152    // h1 per stream: [32 rows][256 k] fp16 = 16384 x4
#define PART_OFF  114688   // per stream: [32 rows][4 cb] fp32 = 512 x4
#define SMEM_TOTAL 116736

// ---------------------------------------------------------------- helpers
static __device__ __forceinline__ uint32_t smem_u32(const void* p) {
    uint32_t a;
    asm("{ .reg .u64 t; cvta.to.shared.u64 t, %1; cvt.u32.u64 %0, t; }"
        : "=r"(a) : "l"(p));
    return a;
}

static __device__ __forceinline__ void bar_stream(int id) {
    // named barrier, 128 threads (4 warps of one stream)
    asm volatile("bar.sync %0, 128;" :: "r"(id) : "memory");
}

static __device__ __forceinline__ void ldm_x4(uint32_t (&r)[4], uint32_t addr) {
    asm volatile("ldmatrix.sync.aligned.m8n8.x4.shared.b16 {%0,%1,%2,%3}, [%4];"
        : "=r"(r[0]), "=r"(r[1]), "=r"(r[2]), "=r"(r[3]) : "r"(addr));
}

static __device__ __forceinline__ void mma_f16(float (&d)[4],
                                               const uint32_t (&a)[4],
                                               uint32_t b0, uint32_t b1) {
    asm volatile(
        "mma.sync.aligned.m16n8k16.row.col.f32.f16.f16.f32 "
        "{%0,%1,%2,%3}, {%4,%5,%6,%7}, {%8,%9}, {%0,%1,%2,%3};"
        : "+f"(d[0]), "+f"(d[1]), "+f"(d[2]), "+f"(d[3])
        : "r"(a[0]), "r"(a[1]), "r"(a[2]), "r"(a[3]), "r"(b0), "r"(b1));
}

static __device__ __forceinline__ uint32_t packhf(float v0, float v1) {
    __half h0 = __float2half_rn(v0);
    __half h1 = __float2half_rn(v1);
    return (uint32_t)__half_as_ushort(h0)
         | ((uint32_t)__half_as_ushort(h1) << 16);
}

// ---------------------------------------------------------------- prologues
// Pack W1 (63x256 per step, + bias row k=63 so v[63]=1 carries b1) into
// mma B-fragment order, fp16.
__global__ void pack_w1(const float* __restrict__ W1,
                        const float* __restrict__ b1, int nsteps)
{
    int t = blockIdx.x * blockDim.x + threadIdx.x;
    // t = ((step*4 + kt)*32 + ntg)*32 + lane
    int lane = t & 31, ntg = (t >> 5) & 31, kt = (t >> 10) & 3;
    int step = t >> 12;
    if (step >= nsteps) return;
    int g = lane >> 2, t2 = lane & 3;
    int n = ntg * 8 + g;
    int k0 = kt * 16 + 2 * t2;
    float w[4];
    #pragma unroll
    for (int e = 0; e < 4; ++e) {
        int k = k0 + (e >> 1) * 8 + (e & 1);
        w[e] = (k < 63) ? W1[((size_t)step * 63 + k) * 256 + n]
                        : b1[step * 256 + n];
    }
    uint2 frag = make_uint2(packhf(w[0], w[1]), packhf(w[2], w[3]));
    size_t off = (((size_t)step * 4 + kt) * 32 + ntg) * 32 + lane;
    *(uint2*)(g_w1f + off * 8) = frag;
}

__global__ void pack_w2(const float* __restrict__ W2, int nsteps)
{
    int t = blockIdx.x * blockDim.x + threadIdx.x;
    int lane = t & 31, ntg = (t >> 5) & 31, kt = (t >> 10) & 15;
    int step = t >> 14;
    if (step >= nsteps) return;
    int g = lane >> 2, t2 = lane & 3;
    int n = ntg * 8 + g;
    int k0 = kt * 16 + 2 * t2;
    float w[4];
    #pragma unroll
    for (int e = 0; e < 4; ++e) {
        int k = k0 + (e >> 1) * 8 + (e & 1);
        w[e] = W2[((size_t)step * 256 + k) * 256 + n];
    }
    uint2 frag = make_uint2(packhf(w[0], w[1]), packhf(w[2], w[3]));
    size_t off = (((size_t)step * 16 + kt) * 32 + ntg) * 32 + lane;
    *(uint2*)(g_w2f + off * 8) = frag;
}

__global__ void pack_bw3(const float* __restrict__ b2,
                         const float* __restrict__ W3, int nsteps)
{
    int t = blockIdx.x * blockDim.x + threadIdx.x;
    int lane = t & 31, ntg = (t >> 5) & 31, step = t >> 10;
    if (step >= nsteps) return;
    int n0 = ntg * 8 + 2 * (lane & 3);
    float4 f = make_float4(b2[step * 256 + n0], b2[step * 256 + n0 + 1],
                           W3[step * 256 + n0], W3[step * 256 + n0 + 1]);
    *(float4*)(g_bw3 + (((size_t)step * 32 + ntg) * 32 + lane) * 16) = f;
}

// ---------------------------------------------------------------- main
__global__ void __launch_bounds__(512, 1)
flow_main_kernel(const float* __restrict__ x,
                 const float* __restrict__ s,
                 const float* __restrict__ b3g,
                 const int*   __restrict__ idx,
                 float* __restrict__ out,
                 int nsteps)
{
    extern __shared__ unsigned char smem[];
    float* zs = (float*)(smem + ZS_OFF);       // [64 cols][128 rows]
    const uint32_t sb = smem_u32(smem);

    const int tid    = threadIdx.x;
    const int lane   = tid & 31;
    const int w      = tid >> 5;        // 0..15
    const int stream = w >> 2;          // 0..3: independent 32-row stream
    const int ws     = w & 3;           // warp within stream = col block
    const int stid   = tid & 127;       // thread id within stream
    const int g      = lane >> 2;
    const int t2     = lane & 3;
    const int r0     = stream * 32;     // first CTA-row of this stream
    const int barid  = stream + 1;      // named barrier id (avoid 0)
    const long long row0 = (long long)blockIdx.x * 128;

    const uint32_t vbase  = sb + VH_OFF + stream * 4096;
    const uint32_t h1base = sb + H1_OFF + stream * 16384;
    float* part = (float*)(smem + PART_OFF + stream * 512);  // [32 rows][4 cb]

    // ldmatrix lane-address components (row/k-half this lane supplies)
    const int lrow  = (lane & 7) + ((lane >> 3) & 1) * 8;  // 0..15 within tile
    const int khalf = (lane >> 4) & 1;                      // 0/1 (k or k+8)

    // Load z tile col-major: zs[c][r] = x[row0+r][c]
    for (int e = tid; e < 128 * 64; e += 512) {
        int c = e & 63, r = e >> 6;
        zs[c * 128 + r] = x[(row0 + r) * 64 + c];
    }
    __syncthreads();

    for (int step = 0; step < nsteps; ++step) {
        const int i = idx[step];

        // ---- build v for this stream's 32 rows (fp16, swizzled)
        {
            const int row  = stid & 31;           // row within stream
            const int quad = stid >> 5;           // 0..3: 16 k-values each
            const int zr   = r0 + row;
            const float z63 = zs[63 * 128 + zr];
            #pragma unroll
            for (int c = 0; c < 2; ++c) {
                const int chunk = quad * 2 + c;   // 8 k-values per chunk
                uint32_t hi[4];
                #pragma unroll
                for (int e = 0; e < 4; ++e) {
                    int k0 = chunk * 8 + 2 * e, k1 = k0 + 1;
                    float v0 = (k0 == 63) ? 1.f
                             : ((k0 == i) ? z63 : zs[k0 * 128 + zr]);
                    float v1 = (k1 == 63) ? 1.f
                             : ((k1 == i) ? z63 : zs[k1 * 128 + zr]);
                    hi[e] = packhf(v0, v1);
                }
                uint32_t off = (uint32_t)row * 128 + ((chunk ^ (row & 7)) << 4);
                *(uint4*)(vbase - sb + smem + off) = make_uint4(hi[0], hi[1], hi[2], hi[3]);
            }
        }
        bar_stream(barid);

        float acc[2][8][4];
        #pragma unroll
        for (int rt = 0; rt < 2; ++rt)
            #pragma unroll
            for (int nt = 0; nt < 8; ++nt)
                #pragma unroll
                for (int e = 0; e < 4; ++e) acc[rt][nt][e] = 0.f;

        // ---- GEMM1: h1 = v @ W1 (+b1 via pad row), K=64
        {
            const unsigned char* wb = g_w1f + (size_t)step * W1_STEP_BYTES;
            #pragma unroll
            for (int kt = 0; kt < 4; ++kt) {
                uint32_t Ah[2][4];
                #pragma unroll
                for (int rt = 0; rt < 2; ++rt) {
                    int row = rt * 16 + lrow;          // 0..31 within stream
                    int chunk = kt * 2 + khalf;
                    uint32_t ad = vbase + (uint32_t)row * 128
                                + ((chunk ^ (row & 7)) << 4);
                    ldm_x4(Ah[rt], ad);
                }
                #pragma unroll
                for (int nt = 0; nt < 8; ++nt) {
                    size_t fi = (((size_t)kt * 32) + ws * 8 + nt) * 32 + lane;
                    uint2 bh = *(const uint2*)(wb + fi * 8);
                    #pragma unroll
                    for (int rt = 0; rt < 2; ++rt)
                        mma_f16(acc[rt][nt], Ah[rt], bh.x, bh.y);
                }
            }
        }

        // ---- epi1: relu, fp16, store h1 (swizzled) for GEMM2's A
        #pragma unroll
        for (int rt = 0; rt < 2; ++rt) {
            #pragma unroll
            for (int h = 0; h < 2; ++h) {
                int row = rt * 16 + g + 8 * h;         // 0..31 within stream
                uint32_t rbase = (uint32_t)row * 512;
                uint32_t sw = (uint32_t)(row & 7);
                #pragma unroll
                for (int nt = 0; nt < 8; ++nt) {
                    float v0 = fmaxf(acc[rt][nt][2 * h],     0.f);
                    float v1 = fmaxf(acc[rt][nt][2 * h + 1], 0.f);
                    uint32_t chunk = (uint32_t)(ws * 8 + nt);
                    uint32_t off = rbase + ((chunk ^ sw) << 4) + 4 * t2;
                    *(uint32_t*)(h1base - sb + smem + off) = packhf(v0, v1);
                }
            }
        }
        bar_stream(barid);

        #pragma unroll
        for (int rt = 0; rt < 2; ++rt)
            #pragma unroll
            for (int nt = 0; nt < 8; ++nt)
                #pragma unroll
                for (int e = 0; e < 4; ++e) acc[rt][nt][e] = 0.f;

        // ---- GEMM2: h2 = h1 @ W2, K=256
        {
            const unsigned char* wb = g_w2f + (size_t)step * W2_STEP_BYTES;
            #pragma unroll 1
            for (int kt = 0; kt < 16; ++kt) {
                uint32_t Ah[2][4];
                #pragma unroll
                for (int rt = 0; rt < 2; ++rt) {
                    int row = rt * 16 + lrow;
                    int chunk = kt * 2 + khalf;
                    uint32_t ad = h1base + (uint32_t)row * 512
                                + ((chunk ^ (row & 7)) << 4);
                    ldm_x4(Ah[rt], ad);
                }
                #pragma unroll
                for (int nt = 0; nt < 8; ++nt) {
                    size_t fi = (((size_t)kt * 32) + ws * 8 + nt) * 32 + lane;
                    uint2 bh = *(const uint2*)(wb + fi * 8);
                    #pragma unroll
                    for (int rt = 0; rt < 2; ++rt)
                        mma_f16(acc[rt][nt], Ah[rt], bh.x, bh.y);
                }
            }
        }

        // ---- GEMM3: t[r] = b3 + sum_n relu(h2[r,n] + b2[n]) * w3[n]
        {
            float p0[2], p1[2];   // per-lane row partials: rows g and g+8, per rt
            #pragma unroll
            for (int rt = 0; rt < 2; ++rt) { p0[rt] = 0.f; p1[rt] = 0.f; }
            #pragma unroll
            for (int nt = 0; nt < 8; ++nt) {
                float4 bw = *(const float4*)(g_bw3 +
                    (((size_t)step * 32 + ws * 8 + nt) * 32 + lane) * 16);
                #pragma unroll
                for (int rt = 0; rt < 2; ++rt) {
                    p0[rt] = fmaf(fmaxf(acc[rt][nt][0] + bw.x, 0.f), bw.z, p0[rt]);
                    p0[rt] = fmaf(fmaxf(acc[rt][nt][1] + bw.y, 0.f), bw.w, p0[rt]);
                    p1[rt] = fmaf(fmaxf(acc[rt][nt][2] + bw.x, 0.f), bw.z, p1[rt]);
                    p1[rt] = fmaf(fmaxf(acc[rt][nt][3] + bw.y, 0.f), bw.w, p1[rt]);
                }
            }
            #pragma unroll
            for (int rt = 0; rt < 2; ++rt) {
                #pragma unroll
                for (int o = 1; o < 4; o <<= 1) {
                    p0[rt] += __shfl_xor_sync(0xffffffffu, p0[rt], o);
                    p1[rt] += __shfl_xor_sync(0xffffffffu, p1[rt], o);
                }
                if (t2 == 0) {
                    int rowa = rt * 16 + g;            // 0..31 within stream
                    part[rowa * 4 + ws]       = p0[rt];
                    part[(rowa + 8) * 4 + ws] = p1[rt];
                }
            }
        }
        bar_stream(barid);

        // ---- z update for this stream's rows (warp 0 of the stream)
        if (ws == 0) {
            float t = b3g[step] + part[lane * 4] + part[lane * 4 + 1]
                    + part[lane * 4 + 2] + part[lane * 4 + 3];
            const int tgt = (i < 63) ? i : 63;
            zs[tgt * 128 + r0 + lane] += t;
        }
        bar_stream(barid);
    }

    __syncthreads();

    // Epilogue: out = exp(s) * z
    for (int e = tid; e < 128 * 64; e += 512) {
        int c = e & 63, r = e >> 6;
        out[(row0 + r) * 64 + c] = expf(s[c]) * zs[c * 128 + r];
    }
}

// ---------------------------------------------------------------- launch
extern "C" void kernel_launch(void* const* d_in, const int* in_sizes, int n_in,
                              void* d_out, int out_size)
{
    const float* x   = (const float*)d_in[0];
    const float* s   = (const float*)d_in[1];
    const float* W1  = (const float*)d_in[2];
    const float* b1  = (const float*)d_in[3];
    const float* W2  = (const float*)d_in[4];
    const float* b2  = (const float*)d_in[5];
    const float* W3  = (const float*)d_in[6];
    const float* b3  = (const float*)d_in[7];
    const int*   idx = (const int*)d_in[8];
    float* out = (float*)d_out;

    const int B      = in_sizes[0] / 64;     // 131072
    const int nsteps = in_sizes[8];          // 65

    // Prologues: pack weights into MMA-fragment order (fp16)
    {
        int t1 = nsteps * 4 * 32 * 32;            // 266240
        pack_w1<<<(t1 + 255) / 256, 256>>>(W1, b1, nsteps);
        int t2 = nsteps * 16 * 32 * 32;           // 1064960
        pack_w2<<<(t2 + 255) / 256, 256>>>(W2, nsteps);
        int t3 = nsteps * 32 * 32;                // 66560
        pack_bw3<<<(t3 + 255) / 256, 256>>>(b2, W3, nsteps);
    }

    cudaFuncSetAttribute(flow_main_kernel,
                         cudaFuncAttributeMaxDynamicSharedMemorySize, SMEM_TOTAL);

    dim3 grid(B / 128);   // 1024 CTAs
    dim3 block(512);
    flow_main_kernel<<<grid, block, SMEM_TOTAL>>>(
        x, s, b3, idx, out, nsteps);
}

// round 16
// speedup vs baseline: 1.0003x; 1.0003x over previous
#include <cuda_runtime.h>
#include <cuda_fp16.h>
#include <stdint.h>

// ============================================================================
// Additive flow: 65 sequential steps of a 63->256->256->1 MLP per batch row.
// Warp-level mma.sync.m16n8k16 fp16 (HMMA), single product (A and W rounded
// once to fp16, fp32 accumulate; measured rel_err ~1.9e-4, 5x under gate).
// Weights pre-packed into per-lane MMA fragment order by prologue kernels so
// B operands are coalesced LDG.64s shared across CTAs (L1/L2 broadcast).
//
// This round: ONE 512-thread CTA per SM containing FOUR independent 4-warp
// streams, each owning 32 batch rows. Streams synchronize only via their own
// named barrier (bar.sync id,128) -- no CTA-wide __syncthreads in the step
// loop -- so one stream's MMA phase overlaps another's epilogue phase and the
// tensor pipe (previously idle 43% of the time) stays fed.
// ============================================================================

#define NSTEPS_MAX 65

// W1 fragments: [step][kt(4)][ntile(32)][lane(32)] x 8B   (fp16)
__device__ __align__(16) unsigned char g_w1f[NSTEPS_MAX * 4 * 32 * 32 * 8];
// W2 fragments: [step][kt(16)][ntile(32)][lane(32)] x 8B
__device__ __align__(16) unsigned char g_w2f[(size_t)NSTEPS_MAX * 16 * 32 * 32 * 8];
// [step][ntile(32)][lane(32)] x float4 {b2[n0], b2[n0+1], w3[n0], w3[n0+1]}
__device__ __align__(16) unsigned char g_bw3[NSTEPS_MAX * 32 * 32 * 16];

#define W1_STEP_BYTES  (4 * 32 * 32 * 8)     // 32768
#define W2_STEP_BYTES  (16 * 32 * 32 * 8)    // 131072

// ---- SMEM layout (bytes), 128-row CTA tile = 4 streams x 32 rows ----
#define ZS_OFF    0        // z: [64 cols][128 rows] fp32 = 32768
#define VH_OFF    32768    // v per stream: [32 rows][64 k] fp16 = 4096 x4
#define H1_OFF    49152    // h1 per stream: [32 rows][256 k] fp16 = 16384 x4
#define PART_OFF  114688   // per stream: [32 rows][4 cb] fp32 = 512 x4
#define SMEM_TOTAL 116736

// ---------------------------------------------------------------- helpers
static __device__ __forceinline__ uint32_t smem_u32(const void* p) {
    uint32_t a;
    asm("{ .reg .u64 t; cvta.to.shared.u64 t, %1; cvt.u32.u64 %0, t; }"
        : "=r"(a) : "l"(p));
    return a;
}

static __device__ __forceinline__ void bar_stream(int id) {
    // named barrier, 128 threads (4 warps of one stream)
    asm volatile("bar.sync %0, 128;" :: "r"(id) : "memory");
}

static __device__ __forceinline__ void ldm_x4(uint32_t (&r)[4], uint32_t addr) {
    asm volatile("ldmatrix.sync.aligned.m8n8.x4.shared.b16 {%0,%1,%2,%3}, [%4];"
        : "=r"(r[0]), "=r"(r[1]), "=r"(r[2]), "=r"(r[3]) : "r"(addr));
}

static __device__ __forceinline__ void mma_f16(float (&d)[4],
                                               const uint32_t (&a)[4],
                                               uint32_t b0, uint32_t b1) {
    asm volatile(
        "mma.sync.aligned.m16n8k16.row.col.f32.f16.f16.f32 "
        "{%0,%1,%2,%3}, {%4,%5,%6,%7}, {%8,%9}, {%0,%1,%2,%3};"
        : "+f"(d[0]), "+f"(d[1]), "+f"(d[2]), "+f"(d[3])
        : "r"(a[0]), "r"(a[1]), "r"(a[2]), "r"(a[3]), "r"(b0), "r"(b1));
}

static __device__ __forceinline__ uint32_t packhf(float v0, float v1) {
    __half h0 = __float2half_rn(v0);
    __half h1 = __float2half_rn(v1);
    return (uint32_t)__half_as_ushort(h0)
         | ((uint32_t)__half_as_ushort(h1) << 16);
}

// ---------------------------------------------------------------- prologues
// Pack W1 (63x256 per step, + bias row k=63 so v[63]=1 carries b1) into
// mma B-fragment order, fp16.
__global__ void pack_w1(const float* __restrict__ W1,
                        const float* __restrict__ b1, int nsteps)
{
    int t = blockIdx.x * blockDim.x + threadIdx.x;
    // t = ((step*4 + kt)*32 + ntg)*32 + lane
    int lane = t & 31, ntg = (t >> 5) & 31, kt = (t >> 10) & 3;
    int step = t >> 12;
    if (step >= nsteps) return;
    int g = lane >> 2, t2 = lane & 3;
    int n = ntg * 8 + g;
    int k0 = kt * 16 + 2 * t2;
    float w[4];
    #pragma unroll
    for (int e = 0; e < 4; ++e) {
        int k = k0 + (e >> 1) * 8 + (e & 1);
        w[e] = (k < 63) ? W1[((size_t)step * 63 + k) * 256 + n]
                        : b1[step * 256 + n];
    }
    uint2 frag = make_uint2(packhf(w[0], w[1]), packhf(w[2], w[3]));
    size_t off = (((size_t)step * 4 + kt) * 32 + ntg) * 32 + lane;
    *(uint2*)(g_w1f + off * 8) = frag;
}

__global__ void pack_w2(const float* __restrict__ W2, int nsteps)
{
    int t = blockIdx.x * blockDim.x + threadIdx.x;
    int lane = t & 31, ntg = (t >> 5) & 31, kt = (t >> 10) & 15;
    int step = t >> 14;
    if (step >= nsteps) return;
    int g = lane >> 2, t2 = lane & 3;
    int n = ntg * 8 + g;
    int k0 = kt * 16 + 2 * t2;
    float w[4];
    #pragma unroll
    for (int e = 0; e < 4; ++e) {
        int k = k0 + (e >> 1) * 8 + (e & 1);
        w[e] = W2[((size_t)step * 256 + k) * 256 + n];
    }
    uint2 frag = make_uint2(packhf(w[0], w[1]), packhf(w[2], w[3]));
    size_t off = (((size_t)step * 16 + kt) * 32 + ntg) * 32 + lane;
    *(uint2*)(g_w2f + off * 8) = frag;
}

__global__ void pack_bw3(const float* __restrict__ b2,
                         const float* __restrict__ W3, int nsteps)
{
    int t = blockIdx.x * blockDim.x + threadIdx.x;
    int lane = t & 31, ntg = (t >> 5) & 31, step = t >> 10;
    if (step >= nsteps) return;
    int n0 = ntg * 8 + 2 * (lane & 3);
    float4 f = make_float4(b2[step * 256 + n0], b2[step * 256 + n0 + 1],
                           W3[step * 256 + n0], W3[step * 256 + n0 + 1]);
    *(float4*)(g_bw3 + (((size_t)step * 32 + ntg) * 32 + lane) * 16) = f;
}

// ---------------------------------------------------------------- main
__global__ void __launch_bounds__(512, 1)
flow_main_kernel(const float* __restrict__ x,
                 const float* __restrict__ s,
                 const float* __restrict__ b3g,
                 const int*   __restrict__ idx,
                 float* __restrict__ out,
                 int nsteps)
{
    extern __shared__ unsigned char smem[];
    float* zs = (float*)(smem + ZS_OFF);       // [64 cols][128 rows]
    const uint32_t sb = smem_u32(smem);

    const int tid    = threadIdx.x;
    const int lane   = tid & 31;
    const int w      = tid >> 5;        // 0..15
    const int stream = w >> 2;          // 0..3: independent 32-row stream
    const int ws     = w & 3;           // warp within stream = col block
    const int stid   = tid & 127;       // thread id within stream
    const int g      = lane >> 2;
    const int t2     = lane & 3;
    const int r0     = stream * 32;     // first CTA-row of this stream
    const int barid  = stream + 1;      // named barrier id (avoid 0)
    const long long row0 = (long long)blockIdx.x * 128;

    const uint32_t vbase  = sb + VH_OFF + stream * 4096;
    const uint32_t h1base = sb + H1_OFF + stream * 16384;
    float* part = (float*)(smem + PART_OFF + stream * 512);  // [32 rows][4 cb]

    // ldmatrix lane-address components (row/k-half this lane supplies)
    const int lrow  = (lane & 7) + ((lane >> 3) & 1) * 8;  // 0..15 within tile
    const int khalf = (lane >> 4) & 1;                      // 0/1 (k or k+8)

    // Load z tile col-major: zs[c][r] = x[row0+r][c]
    for (int e = tid; e < 128 * 64; e += 512) {
        int c = e & 63, r = e >> 6;
        zs[c * 128 + r] = x[(row0 + r) * 64 + c];
    }
    __syncthreads();

    for (int step = 0; step < nsteps; ++step) {
        const int i = idx[step];

        // ---- build v for this stream's 32 rows (fp16, swizzled)
        {
            const int row  = stid & 31;           // row within stream
            const int quad = stid >> 5;           // 0..3: 16 k-values each
            const int zr   = r0 + row;
            const float z63 = zs[63 * 128 + zr];
            #pragma unroll
            for (int c = 0; c < 2; ++c) {
                const int chunk = quad * 2 + c;   // 8 k-values per chunk
                uint32_t hi[4];
                #pragma unroll
                for (int e = 0; e < 4; ++e) {
                    int k0 = chunk * 8 + 2 * e, k1 = k0 + 1;
                    float v0 = (k0 == 63) ? 1.f
                             : ((k0 == i) ? z63 : zs[k0 * 128 + zr]);
                    float v1 = (k1 == 63) ? 1.f
                             : ((k1 == i) ? z63 : zs[k1 * 128 + zr]);
                    hi[e] = packhf(v0, v1);
                }
                uint32_t off = (uint32_t)row * 128 + ((chunk ^ (row & 7)) << 4);
                *(uint4*)(vbase - sb + smem + off) = make_uint4(hi[0], hi[1], hi[2], hi[3]);
            }
        }
        bar_stream(barid);

        float acc[2][8][4];
        #pragma unroll
        for (int rt = 0; rt < 2; ++rt)
            #pragma unroll
            for (int nt = 0; nt < 8; ++nt)
                #pragma unroll
                for (int e = 0; e < 4; ++e) acc[rt][nt][e] = 0.f;

        // ---- GEMM1: h1 = v @ W1 (+b1 via pad row), K=64
        {
            const unsigned char* wb = g_w1f + (size_t)step * W1_STEP_BYTES;
            #pragma unroll
            for (int kt = 0; kt < 4; ++kt) {
                uint32_t Ah[2][4];
                #pragma unroll
                for (int rt = 0; rt < 2; ++rt) {
                    int row = rt * 16 + lrow;          // 0..31 within stream
                    int chunk = kt * 2 + khalf;
                    uint32_t ad = vbase + (uint32_t)row * 128
                                + ((chunk ^ (row & 7)) << 4);
                    ldm_x4(Ah[rt], ad);
                }
                #pragma unroll
                for (int nt = 0; nt < 8; ++nt) {
                    size_t fi = (((size_t)kt * 32) + ws * 8 + nt) * 32 + lane;
                    uint2 bh = *(const uint2*)(wb + fi * 8);
                    #pragma unroll
                    for (int rt = 0; rt < 2; ++rt)
                        mma_f16(acc[rt][nt], Ah[rt], bh.x, bh.y);
                }
            }
        }

        // ---- epi1: relu, fp16, store h1 (swizzled) for GEMM2's A
        #pragma unroll
        for (int rt = 0; rt < 2; ++rt) {
            #pragma unroll
            for (int h = 0; h < 2; ++h) {
                int row = rt * 16 + g + 8 * h;         // 0..31 within stream
                uint32_t rbase = (uint32_t)row * 512;
                uint32_t sw = (uint32_t)(row & 7);
                #pragma unroll
                for (int nt = 0; nt < 8; ++nt) {
                    float v0 = fmaxf(acc[rt][nt][2 * h],     0.f);
                    float v1 = fmaxf(acc[rt][nt][2 * h + 1], 0.f);
                    uint32_t chunk = (uint32_t)(ws * 8 + nt);
                    uint32_t off = rbase + ((chunk ^ sw) << 4) + 4 * t2;
                    *(uint32_t*)(h1base - sb + smem + off) = packhf(v0, v1);
                }
            }
        }
        bar_stream(barid);

        #pragma unroll
        for (int rt = 0; rt < 2; ++rt)
            #pragma unroll
            for (int nt = 0; nt < 8; ++nt)
                #pragma unroll
                for (int e = 0; e < 4; ++e) acc[rt][nt][e] = 0.f;

        // ---- GEMM2: h2 = h1 @ W2, K=256
        {
            const unsigned char* wb = g_w2f + (size_t)step * W2_STEP_BYTES;
            #pragma unroll 1
            for (int kt = 0; kt < 16; ++kt) {
                uint32_t Ah[2][4];
                #pragma unroll
                for (int rt = 0; rt < 2; ++rt) {
                    int row = rt * 16 + lrow;
                    int chunk = kt * 2 + khalf;
                    uint32_t ad = h1base + (uint32_t)row * 512
                                + ((chunk ^ (row & 7)) << 4);
                    ldm_x4(Ah[rt], ad);
                }
                #pragma unroll
                for (int nt = 0; nt < 8; ++nt) {
                    size_t fi = (((size_t)kt * 32) + ws * 8 + nt) * 32 + lane;
                    uint2 bh = *(const uint2*)(wb + fi * 8);
                    #pragma unroll
                    for (int rt = 0; rt < 2; ++rt)
                        mma_f16(acc[rt][nt], Ah[rt], bh.x, bh.y);
                }
            }
        }

        // ---- GEMM3: t[r] = b3 + sum_n relu(h2[r,n] + b2[n]) * w3[n]
        {
            float p0[2], p1[2];   // per-lane row partials: rows g and g+8, per rt
            #pragma unroll
            for (int rt = 0; rt < 2; ++rt) { p0[rt] = 0.f; p1[rt] = 0.f; }
            #pragma unroll
            for (int nt = 0; nt < 8; ++nt) {
                float4 bw = *(const float4*)(g_bw3 +
                    (((size_t)step * 32 + ws * 8 + nt) * 32 + lane) * 16);
                #pragma unroll
                for (int rt = 0; rt < 2; ++rt) {
                    p0[rt] = fmaf(fmaxf(acc[rt][nt][0] + bw.x, 0.f), bw.z, p0[rt]);
                    p0[rt] = fmaf(fmaxf(acc[rt][nt][1] + bw.y, 0.f), bw.w, p0[rt]);
                    p1[rt] = fmaf(fmaxf(acc[rt][nt][2] + bw.x, 0.f), bw.z, p1[rt]);
                    p1[rt] = fmaf(fmaxf(acc[rt][nt][3] + bw.y, 0.f), bw.w, p1[rt]);
                }
            }
            #pragma unroll
            for (int rt = 0; rt < 2; ++rt) {
                #pragma unroll
                for (int o = 1; o < 4; o <<= 1) {
                    p0[rt] += __shfl_xor_sync(0xffffffffu, p0[rt], o);
                    p1[rt] += __shfl_xor_sync(0xffffffffu, p1[rt], o);
                }
                if (t2 == 0) {
                    int rowa = rt * 16 + g;            // 0..31 within stream
                    part[rowa * 4 + ws]       = p0[rt];
                    part[(rowa + 8) * 4 + ws] = p1[rt];
                }
            }
        }
        bar_stream(barid);

        // ---- z update for this stream's rows (warp 0 of the stream)
        if (ws == 0) {
            float t = b3g[step] + part[lane * 4] + part[lane * 4 + 1]
                    + part[lane * 4 + 2] + part[lane * 4 + 3];
            const int tgt = (i < 63) ? i : 63;
            zs[tgt * 128 + r0 + lane] += t;
        }
        bar_stream(barid);
    }

    __syncthreads();

    // Epilogue: out = exp(s) * z
    for (int e = tid; e < 128 * 64; e += 512) {
        int c = e & 63, r = e >> 6;
        out[(row0 + r) * 64 + c] = expf(s[c]) * zs[c * 128 + r];
    }
}

// ---------------------------------------------------------------- launch
extern "C" void kernel_launch(void* const* d_in, const int* in_sizes, int n_in,
                              void* d_out, int out_size)
{
    const float* x   = (const float*)d_in[0];
    const float* s   = (const float*)d_in[1];
    const float* W1  = (const float*)d_in[2];
    const float* b1  = (const float*)d_in[3];
    const float* W2  = (const float*)d_in[4];
    const float* b2  = (const float*)d_in[5];
    const float* W3  = (const float*)d_in[6];
    const float* b3  = (const float*)d_in[7];
    const int*   idx = (const int*)d_in[8];
    float* out = (float*)d_out;

    const int B      = in_sizes[0] / 64;     // 131072
    const int nsteps = in_sizes[8];          // 65

    // Prologues: pack weights into MMA-fragment order (fp16)
    {
        int t1 = nsteps * 4 * 32 * 32;            // 266240
        pack_w1<<<(t1 + 255) / 256, 256>>>(W1, b1, nsteps);
        int t2 = nsteps * 16 * 32 * 32;           // 1064960
        pack_w2<<<(t2 + 255) / 256, 256>>>(W2, nsteps);
        int t3 = nsteps * 32 * 32;                // 66560
        pack_bw3<<<(t3 + 255) / 256, 256>>>(b2, W3, nsteps);
    }

    cudaFuncSetAttribute(flow_main_kernel,
                         cudaFuncAttributeMaxDynamicSharedMemorySize, SMEM_TOTAL);

    dim3 grid(B / 128);   // 1024 CTAs
    dim3 block(512);
    flow_main_kernel<<<grid, block, SMEM_TOTAL>>>(
        x, s, b3, idx, out, nsteps);
}

// round 17
// speedup vs baseline: 1.0018x; 1.0015x over previous
#include <cuda_runtime.h>
#include <cuda_fp16.h>
#include <stdint.h>

// ============================================================================
// Additive flow: 65 sequential steps of a 63->256->256->1 MLP per batch row.
// Warp-level mma.sync.m16n8k16 fp16 (HMMA), single product (A and W rounded
// once to fp16, fp32 accumulate; measured rel_err ~1.9e-4, 5x under gate).
// Weights pre-packed into per-lane MMA fragment order by prologue kernels so
// B operands are coalesced LDG.64s shared across CTAs (L1/L2 broadcast).
//
// This round: ONE 512-thread CTA per SM containing FOUR independent 4-warp
// streams, each owning 32 batch rows. Streams synchronize only via their own
// named barrier (bar.sync id,128) -- no CTA-wide __syncthreads in the step
// loop -- so one stream's MMA phase overlaps another's epilogue phase and the
// tensor pipe (previously idle 43% of the time) stays fed.
// ============================================================================

#define NSTEPS_MAX 65

// W1 fragments: [step][kt(4)][ntile(32)][lane(32)] x 8B   (fp16)
__device__ __align__(16) unsigned char g_w1f[NSTEPS_MAX * 4 * 32 * 32 * 8];
// W2 fragments: [step][kt(16)][ntile(32)][lane(32)] x 8B
__device__ __align__(16) unsigned char g_w2f[(size_t)NSTEPS_MAX * 16 * 32 * 32 * 8];
// [step][ntile(32)][lane(32)] x float4 {b2[n0], b2[n0+1], w3[n0], w3[n0+1]}
__device__ __align__(16) unsigned char g_bw3[NSTEPS_MAX * 32 * 32 * 16];

#define W1_STEP_BYTES  (4 * 32 * 32 * 8)     // 32768
#define W2_STEP_BYTES  (16 * 32 * 32 * 8)    // 131072

// ---- SMEM layout (bytes), 128-row CTA tile = 4 streams x 32 rows ----
#define ZS_OFF    0        // z: [64 cols][128 rows] fp32 = 32768
#define VH_OFF    32768    // v per stream: [32 rows][64 k] fp16 = 4096 x4
#define H1_OFF    49152    // h1 per stream: [32 rows][256 k] fp16 = 16384 x4
#define PART_OFF  114688   // per stream: [32 rows][4 cb] fp32 = 512 x4
#define SMEM_TOTAL 116736

// ---------------------------------------------------------------- helpers
static __device__ __forceinline__ uint32_t smem_u32(const void* p) {
    uint32_t a;
    asm("{ .reg .u64 t; cvta.to.shared.u64 t, %1; cvt.u32.u64 %0, t; }"
        : "=r"(a) : "l"(p));
    return a;
}

static __device__ __forceinline__ void bar_stream(int id) {
    // named barrier, 128 threads (4 warps of one stream)
    asm volatile("bar.sync %0, 128;" :: "r"(id) : "memory");
}

static __device__ __forceinline__ void ldm_x4(uint32_t (&r)[4], uint32_t addr) {
    asm volatile("ldmatrix.sync.aligned.m8n8.x4.shared.b16 {%0,%1,%2,%3}, [%4];"
        : "=r"(r[0]), "=r"(r[1]), "=r"(r[2]), "=r"(r[3]) : "r"(addr));
}

static __device__ __forceinline__ void mma_f16(float (&d)[4],
                                               const uint32_t (&a)[4],
                                               uint32_t b0, uint32_t b1) {
    asm volatile(
        "mma.sync.aligned.m16n8k16.row.col.f32.f16.f16.f32 "
        "{%0,%1,%2,%3}, {%4,%5,%6,%7}, {%8,%9}, {%0,%1,%2,%3};"
        : "+f"(d[0]), "+f"(d[1]), "+f"(d[2]), "+f"(d[3])
        : "r"(a[0]), "r"(a[1]), "r"(a[2]), "r"(a[3]), "r"(b0), "r"(b1));
}

static __device__ __forceinline__ uint32_t packhf(float v0, float v1) {
    __half h0 = __float2half_rn(v0);
    __half h1 = __float2half_rn(v1);
    return (uint32_t)__half_as_ushort(h0)
         | ((uint32_t)__half_as_ushort(h1) << 16);
}

// ---------------------------------------------------------------- prologues
// Pack W1 (63x256 per step, + bias row k=63 so v[63]=1 carries b1) into
// mma B-fragment order, fp16.
__global__ void pack_w1(const float* __restrict__ W1,
                        const float* __restrict__ b1, int nsteps)
{
    int t = blockIdx.x * blockDim.x + threadIdx.x;
    // t = ((step*4 + kt)*32 + ntg)*32 + lane
    int lane = t & 31, ntg = (t >> 5) & 31, kt = (t >> 10) & 3;
    int step = t >> 12;
    if (step >= nsteps) return;
    int g = lane >> 2, t2 = lane & 3;
    int n = ntg * 8 + g;
    int k0 = kt * 16 + 2 * t2;
    float w[4];
    #pragma unroll
    for (int e = 0; e < 4; ++e) {
        int k = k0 + (e >> 1) * 8 + (e & 1);
        w[e] = (k < 63) ? W1[((size_t)step * 63 + k) * 256 + n]
                        : b1[step * 256 + n];
    }
    uint2 frag = make_uint2(packhf(w[0], w[1]), packhf(w[2], w[3]));
    size_t off = (((size_t)step * 4 + kt) * 32 + ntg) * 32 + lane;
    *(uint2*)(g_w1f + off * 8) = frag;
}

__global__ void pack_w2(const float* __restrict__ W2, int nsteps)
{
    int t = blockIdx.x * blockDim.x + threadIdx.x;
    int lane = t & 31, ntg = (t >> 5) & 31, kt = (t >> 10) & 15;
    int step = t >> 14;
    if (step >= nsteps) return;
    int g = lane >> 2, t2 = lane & 3;
    int n = ntg * 8 + g;
    int k0 = kt * 16 + 2 * t2;
    float w[4];
    #pragma unroll
    for (int e = 0; e < 4; ++e) {
        int k = k0 + (e >> 1) * 8 + (e & 1);
        w[e] = W2[((size_t)step * 256 + k) * 256 + n];
    }
    uint2 frag = make_uint2(packhf(w[0], w[1]), packhf(w[2], w[3]));
    size_t off = (((size_t)step * 16 + kt) * 32 + ntg) * 32 + lane;
    *(uint2*)(g_w2f + off * 8) = frag;
}

__global__ void pack_bw3(const float* __restrict__ b2,
                         const float* __restrict__ W3, int nsteps)
{
    int t = blockIdx.x * blockDim.x + threadIdx.x;
    int lane = t & 31, ntg = (t >> 5) & 31, step = t >> 10;
    if (step >= nsteps) return;
    int n0 = ntg * 8 + 2 * (lane & 3);
    float4 f = make_float4(b2[step * 256 + n0], b2[step * 256 + n0 + 1],
                           W3[step * 256 + n0], W3[step * 256 + n0 + 1]);
    *(float4*)(g_bw3 + (((size_t)step * 32 + ntg) * 32 + lane) * 16) = f;
}

// ---------------------------------------------------------------- main
__global__ void __launch_bounds__(512, 1)
flow_main_kernel(const float* __restrict__ x,
                 const float* __restrict__ s,
                 const float* __restrict__ b3g,
                 const int*   __restrict__ idx,
                 float* __restrict__ out,
                 int nsteps)
{
    extern __shared__ unsigned char smem[];
    float* zs = (float*)(smem + ZS_OFF);       // [64 cols][128 rows]
    const uint32_t sb = smem_u32(smem);

    const int tid    = threadIdx.x;
    const int lane   = tid & 31;
    const int w      = tid >> 5;        // 0..15
    const int stream = w >> 2;          // 0..3: independent 32-row stream
    const int ws     = w & 3;           // warp within stream = col block
    const int stid   = tid & 127;       // thread id within stream
    const int g      = lane >> 2;
    const int t2     = lane & 3;
    const int r0     = stream * 32;     // first CTA-row of this stream
    const int barid  = stream + 1;      // named barrier id (avoid 0)
    const long long row0 = (long long)blockIdx.x * 128;

    const uint32_t vbase  = sb + VH_OFF + stream * 4096;
    const uint32_t h1base = sb + H1_OFF + stream * 16384;
    float* part = (float*)(smem + PART_OFF + stream * 512);  // [32 rows][4 cb]

    // ldmatrix lane-address components (row/k-half this lane supplies)
    const int lrow  = (lane & 7) + ((lane >> 3) & 1) * 8;  // 0..15 within tile
    const int khalf = (lane >> 4) & 1;                      // 0/1 (k or k+8)

    // Load z tile col-major: zs[c][r] = x[row0+r][c]
    for (int e = tid; e < 128 * 64; e += 512) {
        int c = e & 63, r = e >> 6;
        zs[c * 128 + r] = x[(row0 + r) * 64 + c];
    }
    __syncthreads();

    for (int step = 0; step < nsteps; ++step) {
        const int i = idx[step];

        // ---- build v for this stream's 32 rows (fp16, swizzled)
        {
            const int row  = stid & 31;           // row within stream
            const int quad = stid >> 5;           // 0..3: 16 k-values each
            const int zr   = r0 + row;
            const float z63 = zs[63 * 128 + zr];
            #pragma unroll
            for (int c = 0; c < 2; ++c) {
                const int chunk = quad * 2 + c;   // 8 k-values per chunk
                uint32_t hi[4];
                #pragma unroll
                for (int e = 0; e < 4; ++e) {
                    int k0 = chunk * 8 + 2 * e, k1 = k0 + 1;
                    float v0 = (k0 == 63) ? 1.f
                             : ((k0 == i) ? z63 : zs[k0 * 128 + zr]);
                    float v1 = (k1 == 63) ? 1.f
                             : ((k1 == i) ? z63 : zs[k1 * 128 + zr]);
                    hi[e] = packhf(v0, v1);
                }
                uint32_t off = (uint32_t)row * 128 + ((chunk ^ (row & 7)) << 4);
                *(uint4*)(vbase - sb + smem + off) = make_uint4(hi[0], hi[1], hi[2], hi[3]);
            }
        }
        bar_stream(barid);

        float acc[2][8][4];
        #pragma unroll
        for (int rt = 0; rt < 2; ++rt)
            #pragma unroll
            for (int nt = 0; nt < 8; ++nt)
                #pragma unroll
                for (int e = 0; e < 4; ++e) acc[rt][nt][e] = 0.f;

        // ---- GEMM1: h1 = v @ W1 (+b1 via pad row), K=64
        {
            const unsigned char* wb = g_w1f + (size_t)step * W1_STEP_BYTES;
            #pragma unroll
            for (int kt = 0; kt < 4; ++kt) {
                uint32_t Ah[2][4];
                #pragma unroll
                for (int rt = 0; rt < 2; ++rt) {
                    int row = rt * 16 + lrow;          // 0..31 within stream
                    int chunk = kt * 2 + khalf;
                    uint32_t ad = vbase + (uint32_t)row * 128
                                + ((chunk ^ (row & 7)) << 4);
                    ldm_x4(Ah[rt], ad);
                }
                #pragma unroll
                for (int nt = 0; nt < 8; ++nt) {
                    size_t fi = (((size_t)kt * 32) + ws * 8 + nt) * 32 + lane;
                    uint2 bh = *(const uint2*)(wb + fi * 8);
                    #pragma unroll
                    for (int rt = 0; rt < 2; ++rt)
                        mma_f16(acc[rt][nt], Ah[rt], bh.x, bh.y);
                }
            }
        }

        // ---- epi1: relu, fp16, store h1 (swizzled) for GEMM2's A
        #pragma unroll
        for (int rt = 0; rt < 2; ++rt) {
            #pragma unroll
            for (int h = 0; h < 2; ++h) {
                int row = rt * 16 + g + 8 * h;         // 0..31 within stream
                uint32_t rbase = (uint32_t)row * 512;
                uint32_t sw = (uint32_t)(row & 7);
                #pragma unroll
                for (int nt = 0; nt < 8; ++nt) {
                    float v0 = fmaxf(acc[rt][nt][2 * h],     0.f);
                    float v1 = fmaxf(acc[rt][nt][2 * h + 1], 0.f);
                    uint32_t chunk = (uint32_t)(ws * 8 + nt);
                    uint32_t off = rbase + ((chunk ^ sw) << 4) + 4 * t2;
                    *(uint32_t*)(h1base - sb + smem + off) = packhf(v0, v1);
                }
            }
        }
        bar_stream(barid);

        #pragma unroll
        for (int rt = 0; rt < 2; ++rt)
            #pragma unroll
            for (int nt = 0; nt < 8; ++nt)
                #pragma unroll
                for (int e = 0; e < 4; ++e) acc[rt][nt][e] = 0.f;

        // ---- GEMM2: h2 = h1 @ W2, K=256
        {
            const unsigned char* wb = g_w2f + (size_t)step * W2_STEP_BYTES;
            #pragma unroll 1
            for (int kt = 0; kt < 16; ++kt) {
                uint32_t Ah[2][4];
                #pragma unroll
                for (int rt = 0; rt < 2; ++rt) {
                    int row = rt * 16 + lrow;
                    int chunk = kt * 2 + khalf;
                    uint32_t ad = h1base + (uint32_t)row * 512
                                + ((chunk ^ (row & 7)) << 4);
                    ldm_x4(Ah[rt], ad);
                }
                #pragma unroll
                for (int nt = 0; nt < 8; ++nt) {
                    size_t fi = (((size_t)kt * 32) + ws * 8 + nt) * 32 + lane;
                    uint2 bh = *(const uint2*)(wb + fi * 8);
                    #pragma unroll
                    for (int rt = 0; rt < 2; ++rt)
                        mma_f16(acc[rt][nt], Ah[rt], bh.x, bh.y);
                }
            }
        }

        // ---- GEMM3: t[r] = b3 + sum_n relu(h2[r,n] + b2[n]) * w3[n]
        {
            float p0[2], p1[2];   // per-lane row partials: rows g and g+8, per rt
            #pragma unroll
            for (int rt = 0; rt < 2; ++rt) { p0[rt] = 0.f; p1[rt] = 0.f; }
            #pragma unroll
            for (int nt = 0; nt < 8; ++nt) {
                float4 bw = *(const float4*)(g_bw3 +
                    (((size_t)step * 32 + ws * 8 + nt) * 32 + lane) * 16);
                #pragma unroll
                for (int rt = 0; rt < 2; ++rt) {
                    p0[rt] = fmaf(fmaxf(acc[rt][nt][0] + bw.x, 0.f), bw.z, p0[rt]);
                    p0[rt] = fmaf(fmaxf(acc[rt][nt][1] + bw.y, 0.f), bw.w, p0[rt]);
                    p1[rt] = fmaf(fmaxf(acc[rt][nt][2] + bw.x, 0.f), bw.z, p1[rt]);
                    p1[rt] = fmaf(fmaxf(acc[rt][nt][3] + bw.y, 0.f), bw.w, p1[rt]);
                }
            }
            #pragma unroll
            for (int rt = 0; rt < 2; ++rt) {
                #pragma unroll
                for (int o = 1; o < 4; o <<= 1) {
                    p0[rt] += __shfl_xor_sync(0xffffffffu, p0[rt], o);
                    p1[rt] += __shfl_xor_sync(0xffffffffu, p1[rt], o);
                }
                if (t2 == 0) {
                    int rowa = rt * 16 + g;            // 0..31 within stream
                    part[rowa * 4 + ws]       = p0[rt];
                    part[(rowa + 8) * 4 + ws] = p1[rt];
                }
            }
        }
        bar_stream(barid);

        // ---- z update for this stream's rows (warp 0 of the stream)
        if (ws == 0) {
            float t = b3g[step] + part[lane * 4] + part[lane * 4 + 1]
                    + part[lane * 4 + 2] + part[lane * 4 + 3];
            const int tgt = (i < 63) ? i : 63;
            zs[tgt * 128 + r0 + lane] += t;
        }
        bar_stream(barid);
    }

    __syncthreads();

    // Epilogue: out = exp(s) * z
    for (int e = tid; e < 128 * 64; e += 512) {
        int c = e & 63, r = e >> 6;
        out[(row0 + r) * 64 + c] = expf(s[c]) * zs[c * 128 + r];
    }
}

// ---------------------------------------------------------------- launch
extern "C" void kernel_launch(void* const* d_in, const int* in_sizes, int n_in,
                              void* d_out, int out_size)
{
    const float* x   = (const float*)d_in[0];
    const float* s   = (const float*)d_in[1];
    const float* W1  = (const float*)d_in[2];
    const float* b1  = (const float*)d_in[3];
    const float* W2  = (const float*)d_in[4];
    const float* b2  = (const float*)d_in[5];
    const float* W3  = (const float*)d_in[6];
    const float* b3  = (const float*)d_in[7];
    const int*   idx = (const int*)d_in[8];
    float* out = (float*)d_out;

    const int B      = in_sizes[0] / 64;     // 131072
    const int nsteps = in_sizes[8];          // 65

    // Prologues: pack weights into MMA-fragment order (fp16)
    {
        int t1 = nsteps * 4 * 32 * 32;            // 266240
        pack_w1<<<(t1 + 255) / 256, 256>>>(W1, b1, nsteps);
        int t2 = nsteps * 16 * 32 * 32;           // 1064960
        pack_w2<<<(t2 + 255) / 256, 256>>>(W2, nsteps);
        int t3 = nsteps * 32 * 32;                // 66560
        pack_bw3<<<(t3 + 255) / 256, 256>>>(b2, W3, nsteps);
    }

    cudaFuncSetAttribute(flow_main_kernel,
                         cudaFuncAttributeMaxDynamicSharedMemorySize, SMEM_TOTAL);

    dim3 grid(B / 128);   // 1024 CTAs
    dim3 block(512);
    flow_main_kernel<<<grid, block, SMEM_TOTAL>>>(
        x, s, b3, idx, out, nsteps);
}